// round 12
// baseline (speedup 1.0000x reference)
#include <cuda_runtime.h>
#include <cuda_bf16.h>
#include <math.h>
#include <cstdint>

#define Tt 96
#define Nn 1024
#define Gg 128
#define Hh 512
#define Ee 32768
#define ENe (Ee + Nn)
#define D2 56
#define INw 64
#define LSTM_CTAS 32
#define NREP 8

// ---------------- scratch ----------------
__device__ __align__(16) float g_XW[(size_t)Tt * Nn * Gg];
__device__ __align__(16) float g_HB[(size_t)Tt * Nn * Gg];
__device__ int   g_offs[Tt * (Nn + 1)];
__device__ __align__(8) int2 g_edge[(size_t)Tt * ENe];   // {src, w as float-bits}
__device__ float g_G2R[NREP * Tt * D2];
__device__ float g_G2[Tt * D2];
__device__ float g_pre[Tt * 4 * Hh];
__device__ float g_hbuf[2 * Hh];
__device__ unsigned g_cnt;

// ---------------- trivial zero kernels (also pad launch index for ncu) ----------------
__global__ void k_zero0() { if (threadIdx.x == 0 && blockIdx.x == 0) g_cnt = 0u; }
__global__ void k_zero1() {
    int i = blockIdx.x * blockDim.x + threadIdx.x;
    if (i < NREP * Tt * D2) g_G2R[i] = 0.f;
}

// ---------------- graph build: histogram + scan + CSR fill, one CTA per t ----------------
__global__ void __launch_bounds__(1024) k_build(const int* __restrict__ ei) {
    int t = blockIdx.x, tid = threadIdx.x;
    __shared__ int sc[Nn];
    __shared__ int cur[Nn];
    __shared__ float sdv[Nn];
    cur[tid] = 0;
    __syncthreads();
    for (int e = tid; e < Ee; e += 1024)
        atomicAdd(&cur[ei[(size_t)t * 2 * Ee + Ee + e] & (Nn - 1)], 1);
    __syncthreads();
    int c = cur[tid] + 1;                       // + self loop
    sdv[tid] = rsqrtf((float)c);
    sc[tid] = c;
    __syncthreads();
    for (int off = 1; off < Nn; off <<= 1) {
        int v = (tid >= off) ? sc[tid - off] : 0;
        __syncthreads();
        sc[tid] += v;
        __syncthreads();
    }
    int ex = sc[tid] - c;
    g_offs[t * (Nn + 1) + tid] = ex;
    if (tid == Nn - 1) g_offs[t * (Nn + 1) + Nn] = sc[tid];
    cur[tid] = ex;
    __syncthreads();
    for (int e = tid; e < ENe; e += 1024) {
        int s, d;
        if (e < Ee) {
            s = ei[(size_t)t * 2 * Ee + e] & (Nn - 1);
            d = ei[(size_t)t * 2 * Ee + Ee + e] & (Nn - 1);
        } else {
            s = d = e - Ee;
        }
        float w = sdv[s] * sdv[d];
        int pos = atomicAdd(&cur[d], 1);
        g_edge[(size_t)t * ENe + pos] = make_int2(s, __float_as_int(w));
    }
}

// ---------------- mma.sync helpers ----------------
__device__ __forceinline__ void mma16816(float* c, const uint32_t* a, uint32_t b0, uint32_t b1) {
    asm volatile(
        "mma.sync.aligned.m16n8k16.row.col.f32.bf16.bf16.f32 "
        "{%0,%1,%2,%3}, {%4,%5,%6,%7}, {%8,%9}, {%0,%1,%2,%3};"
        : "+f"(c[0]), "+f"(c[1]), "+f"(c[2]), "+f"(c[3])
        : "r"(a[0]), "r"(a[1]), "r"(a[2]), "r"(a[3]), "r"(b0), "r"(b1));
}
__device__ __forceinline__ uint32_t packbf2(float x, float y) {
    __nv_bfloat162 h = __floats2bfloat162_rn(x, y);
    return *(uint32_t*)&h;
}

// ---------------- pipelined tensor-core batched GEMM ----------------
#define RS 36
#define BUFW (4 * 128 * RS)
template <int KK, bool EXT>
__global__ void __launch_bounds__(256) k_gemm_mma(const float* __restrict__ Aext,
                                                  const float* __restrict__ B) {
    extern __shared__ uint32_t sm[];

    const int tid = threadIdx.x;
    const int wid = tid >> 5, lane = tid & 31;
    const int warp_m = wid & 3, warp_n = wid >> 2;
    const int t = blockIdx.y;
    const size_t Astr = EXT ? (size_t)Nn * Nn : (size_t)Nn * Gg;
    const float* At = (EXT ? Aext : (const float*)g_HB) + (size_t)t * Astr + (size_t)blockIdx.x * 128 * KK;
    float* Ct = g_XW + ((size_t)t * Nn + (size_t)blockIdx.x * 128) * Gg;

    float acc[2][8][4];
#pragma unroll
    for (int mf = 0; mf < 2; mf++)
#pragma unroll
        for (int nf = 0; nf < 8; nf++)
#pragma unroll
            for (int r = 0; r < 4; r++) acc[mf][nf][r] = 0.f;

    const int lr = lane >> 2;
    const int lk = lane & 3;
    const int r0a = tid >> 4, qa = tid & 15;
    const int k2b = tid >> 7, nb = tid & 127;

    float4 aR[8];
    float2 bR[16];

#pragma unroll
    for (int j = 0; j < 8; j++)
        aR[j] = *(const float4*)(At + (size_t)(r0a + 16 * j) * KK + qa * 4);
#pragma unroll
    for (int j = 0; j < 16; j++) {
        int k = 2 * (k2b + 2 * j);
        bR[j] = make_float2(B[(size_t)k * Gg + nb], B[(size_t)(k + 1) * Gg + nb]);
    }

    constexpr int NK = KK / 64;
    for (int ki = 0; ki < NK; ki++) {
        uint32_t* base = sm + (ki & 1) * BUFW;
        uint32_t* smAh = base;
        uint32_t* smAl = base + 128 * RS;
        uint32_t* smBh = base + 2 * 128 * RS;
        uint32_t* smBl = base + 3 * 128 * RS;

#pragma unroll
        for (int j = 0; j < 8; j++) {
            float4 v = aR[j];
            float hx = __bfloat162float(__float2bfloat16_rn(v.x));
            float hy = __bfloat162float(__float2bfloat16_rn(v.y));
            float hz = __bfloat162float(__float2bfloat16_rn(v.z));
            float hw = __bfloat162float(__float2bfloat16_rn(v.w));
            int idx = (r0a + 16 * j) * RS + qa * 2;
            smAh[idx]     = packbf2(v.x, v.y);
            smAh[idx + 1] = packbf2(v.z, v.w);
            smAl[idx]     = packbf2(v.x - hx, v.y - hy);
            smAl[idx + 1] = packbf2(v.z - hz, v.w - hw);
        }
        {
            int rho = ((nb >> 3) & 3) << 3;
#pragma unroll
            for (int j = 0; j < 16; j++) {
                int k2 = k2b + 2 * j;
                float2 v = bR[j];
                float h0 = __bfloat162float(__float2bfloat16_rn(v.x));
                float h1 = __bfloat162float(__float2bfloat16_rn(v.y));
                int idx = nb * RS + (k2 ^ rho);
                smBh[idx] = packbf2(v.x, v.y);
                smBl[idx] = packbf2(v.x - h0, v.y - h1);
            }
        }
        __syncthreads();

        if (ki + 1 < NK) {
            int k0n = (ki + 1) * 64;
#pragma unroll
            for (int j = 0; j < 8; j++)
                aR[j] = *(const float4*)(At + (size_t)(r0a + 16 * j) * KK + k0n + qa * 4);
#pragma unroll
            for (int j = 0; j < 16; j++) {
                int k = k0n + 2 * (k2b + 2 * j);
                bR[j] = make_float2(B[(size_t)k * Gg + nb], B[(size_t)(k + 1) * Gg + nb]);
            }
        }

#pragma unroll
        for (int ks = 0; ks < 4; ks++) {
            uint32_t ah[2][4], al[2][4];
#pragma unroll
            for (int mf = 0; mf < 2; mf++) {
                int rm = warp_m * 32 + mf * 16 + lr;
                int kw = ks * 8 + lk;
                ah[mf][0] = smAh[rm * RS + kw];
                ah[mf][1] = smAh[(rm + 8) * RS + kw];
                ah[mf][2] = smAh[rm * RS + kw + 4];
                ah[mf][3] = smAh[(rm + 8) * RS + kw + 4];
                al[mf][0] = smAl[rm * RS + kw];
                al[mf][1] = smAl[(rm + 8) * RS + kw];
                al[mf][2] = smAl[rm * RS + kw + 4];
                al[mf][3] = smAl[(rm + 8) * RS + kw + 4];
            }
#pragma unroll
            for (int nf = 0; nf < 8; nf++) {
                int cn = warp_n * 64 + nf * 8 + lr;
                int rho = ((cn >> 3) & 3) << 3;
                int kw = ks * 8 + lk;
                uint32_t bh0 = smBh[cn * RS + (kw ^ rho)];
                uint32_t bh1 = smBh[cn * RS + ((kw + 4) ^ rho)];
                uint32_t bl0 = smBl[cn * RS + (kw ^ rho)];
                uint32_t bl1 = smBl[cn * RS + ((kw + 4) ^ rho)];
#pragma unroll
                for (int mf = 0; mf < 2; mf++) {
                    mma16816(acc[mf][nf], ah[mf], bh0, bh1);
                    mma16816(acc[mf][nf], ah[mf], bl0, bl1);
                    mma16816(acc[mf][nf], al[mf], bh0, bh1);
                }
            }
        }
    }

#pragma unroll
    for (int mf = 0; mf < 2; mf++) {
        int row = warp_m * 32 + mf * 16 + lr;
#pragma unroll
        for (int nf = 0; nf < 8; nf++) {
            int col = warp_n * 64 + nf * 8 + lk * 2;
            float* base = Ct + (size_t)row * Gg + col;
            *(float2*)base = make_float2(acc[mf][nf][0], acc[mf][nf][1]);
            *(float2*)(base + 8 * Gg) = make_float2(acc[mf][nf][2], acc[mf][nf][3]);
        }
    }
}

// ---------------- SpMM v3: smem-cached feature quarter, warp-per-node ----------------
// grid (4, Tt), 256 thr, dyn smem = 1024*33*4 B. X[t] quarter staged in smem;
// per-edge gather becomes 1 conflict-free LDS + 1 FFMA.
#define XS 33
template <bool RELU>
__global__ void __launch_bounds__(256) k_spmm(const float* __restrict__ bias) {
    extern __shared__ float sx[];        // [1024][XS]
    int t = blockIdx.y, q = blockIdx.x;  // feature quarter
    int tid = threadIdx.x, warp = tid >> 5, lane = tid & 31;
    const float* X = g_XW + (size_t)t * Nn * Gg + q * 32;

    // stage quarter: 32 rows per iteration, 8 threads per row (float4)
    int rr = tid >> 3, cc = (tid & 7) * 4;
    for (int r0 = 0; r0 < Nn; r0 += 32) {
        float4 v = *(const float4*)(X + (size_t)(r0 + rr) * Gg + cc);
        float* d = &sx[(r0 + rr) * XS + cc];
        d[0] = v.x; d[1] = v.y; d[2] = v.z; d[3] = v.w;
    }
    __syncthreads();

    const int2* ep = g_edge + (size_t)t * ENe;
    const int* offs = g_offs + t * (Nn + 1);
    float b = bias[q * 32 + lane];

    for (int n = warp; n < Nn; n += 8) {
        int beg = offs[n], end = offs[n + 1];
        float acc = b;
        int e = beg;
        for (; e + 32 <= end; e += 32) {
            int2 er = ep[e + lane];
#pragma unroll
            for (int j = 0; j < 32; j++) {
                int sj = __shfl_sync(0xffffffffu, er.x, j);
                float wj = __uint_as_float(__shfl_sync(0xffffffffu, er.y, j));
                acc += wj * sx[sj * XS + lane];
            }
        }
        if (e < end) {
            int2 er = ep[min(e + lane, end - 1)];
            int cnt = end - e;
            for (int j = 0; j < cnt; j++) {
                int sj = __shfl_sync(0xffffffffu, er.x, j);
                float wj = __uint_as_float(__shfl_sync(0xffffffffu, er.y, j));
                acc += wj * sx[sj * XS + lane];
            }
        }
        if (RELU) acc = fmaxf(acc, 0.f);
        g_HB[((size_t)t * Nn + n) * Gg + q * 32 + lane] = acc;
    }
}

// ---------------- FC: per-node CTA, 4 timesteps/iter, replicated accumulators ----------------
__global__ void __launch_bounds__(256) k_fc(const float* __restrict__ Wfc) {
    int n = blockIdx.x;
    int tid = threadIdx.x;
    __shared__ float Wsm[Gg * D2];
    __shared__ float hs[4][Gg];
    for (int i = tid; i < Gg * D2; i += 256)
        Wsm[i] = Wfc[(size_t)n * Gg * D2 + i];
    __syncthreads();
    int rep = n & (NREP - 1);
    for (int t0 = 0; t0 < Tt; t0 += 4) {
        for (int i = tid; i < 4 * Gg; i += 256)
            hs[i >> 7][i & 127] = g_HB[((size_t)(t0 + (i >> 7)) * Nn + n) * Gg + (i & 127)];
        __syncthreads();
        if (tid < 4 * D2) {
            int tt = tid / D2, d = tid % D2;
            float acc = 0.f;
#pragma unroll 8
            for (int k = 0; k < Gg; k++) acc += hs[tt][k] * Wsm[k * D2 + d];
            atomicAdd(&g_G2R[(rep * Tt + t0 + tt) * D2 + d], acc);
        }
        __syncthreads();
    }
}

// ---------------- sum replicas + bias + relu ----------------
__global__ void k_g2sum(const float* __restrict__ bfc) {
    int i = blockIdx.x * blockDim.x + threadIdx.x;
    if (i >= Tt * D2) return;
    int d = i % D2;
    float s = bfc[d];
#pragma unroll
    for (int r = 0; r < NREP; r++) s += g_G2R[r * Tt * D2 + i];
    g_G2[i] = fmaxf(s, 0.f);
}

// ---------------- LSTM pre-activations ----------------
__global__ void k_pre(const float* __restrict__ x,
                      const float* __restrict__ Wi0, const float* __restrict__ Wi1,
                      const float* __restrict__ Wi2, const float* __restrict__ Wi3,
                      const float* __restrict__ Wg0, const float* __restrict__ Wg1,
                      const float* __restrict__ Wg2, const float* __restrict__ Wg3,
                      const float* __restrict__ b0, const float* __restrict__ b1,
                      const float* __restrict__ b2, const float* __restrict__ b3) {
    int gid = blockIdx.x * blockDim.x + threadIdx.x;
    if (gid >= Tt * 4 * Hh) return;
    int j = gid & (Hh - 1);
    int gate = (gid >> 9) & 3;
    int t = gid >> 11;
    const float* Wi = gate == 0 ? Wi0 : gate == 1 ? Wi1 : gate == 2 ? Wi2 : Wi3;
    const float* Wg = gate == 0 ? Wg0 : gate == 1 ? Wg1 : gate == 2 ? Wg2 : Wg3;
    const float* bb = gate == 0 ? b0 : gate == 1 ? b1 : gate == 2 ? b2 : b3;
    float acc = bb[j];
#pragma unroll 8
    for (int k = 0; k < INw; k++) acc += x[t * INw + k] * Wi[k * Hh + j];
#pragma unroll 8
    for (int d = 0; d < D2; d++) acc += g_G2[t * D2 + d] * Wg[d * Hh + j];
    g_pre[gid] = acc;
}

// ---------------- persistent recurrent LSTM ----------------
__global__ void __launch_bounds__(512, 1) k_lstm(const float* __restrict__ Whi,
                                                 const float* __restrict__ Whf,
                                                 const float* __restrict__ Whg,
                                                 const float* __restrict__ Who,
                                                 float* __restrict__ out, int out_size) {
    int tid = threadIdx.x, warp = tid >> 5, lane = tid & 31;
    int unit = blockIdx.x * 16 + warp;
    int gate = lane >> 3, q = lane & 7;
    const float* Wh = gate == 0 ? Whi : gate == 1 ? Whf : gate == 2 ? Whg : Who;

    float w[64];
#pragma unroll
    for (int mm = 0; mm < 16; mm++)
#pragma unroll
        for (int r = 0; r < 4; r++)
            w[mm * 4 + r] = Wh[(size_t)((q + 8 * mm) * 4 + r) * Hh + unit];

    __shared__ float sh[Hh];
    sh[tid] = 0.f;
    __syncthreads();
    float c = 0.f;

    for (int s = 0; s < Tt; s++) {
        const float4* sh4 = (const float4*)sh;
        float acc = 0.f;
#pragma unroll
        for (int mm = 0; mm < 16; mm++) {
            float4 v = sh4[q + 8 * mm];
            acc += w[mm * 4 + 0] * v.x + w[mm * 4 + 1] * v.y +
                   w[mm * 4 + 2] * v.z + w[mm * 4 + 3] * v.w;
        }
        acc += __shfl_xor_sync(0xffffffffu, acc, 4);
        acc += __shfl_xor_sync(0xffffffffu, acc, 2);
        acc += __shfl_xor_sync(0xffffffffu, acc, 1);
        acc += g_pre[(s * 4 + gate) * Hh + unit];
        float vi = __shfl_sync(0xffffffffu, acc, 0);
        float vf = __shfl_sync(0xffffffffu, acc, 8);
        float vg = __shfl_sync(0xffffffffu, acc, 16);
        float vo = __shfl_sync(0xffffffffu, acc, 24);
        vi = 1.f / (1.f + expf(-vi));
        vf = 1.f / (1.f + expf(-vf));
        vo = 1.f / (1.f + expf(-vo));
        vg = tanhf(vg);
        c = vf * c + vi * vg;
        float h = vo * tanhf(c);
        if (lane == 0) {
            g_hbuf[(s & 1) * Hh + unit] = h;
            if (s * Hh + unit < out_size) out[s * Hh + unit] = h;
            if (s == Tt - 1) {
                if (Tt * Hh + unit < out_size) out[Tt * Hh + unit] = h;
                if (Tt * Hh + Hh + unit < out_size) out[Tt * Hh + Hh + unit] = c;
            }
            __threadfence();
        }
        __syncthreads();
        if (tid == 0) {
            atomicAdd(&g_cnt, 1u);
            unsigned target = (unsigned)(s + 1) * LSTM_CTAS;
            while (*((volatile unsigned*)&g_cnt) < target) {}
            __threadfence();
        }
        __syncthreads();
        sh[tid] = *((volatile float*)&g_hbuf[(s & 1) * Hh + tid]);
        __syncthreads();
    }
}

// ---------------- launch ----------------
extern "C" void kernel_launch(void* const* d_in, const int* in_sizes, int n_in,
                              void* d_out, int out_size) {
    const float* x_in = (const float*)d_in[0];
    const float* xn   = (const float*)d_in[1];
    const int*   ei   = (const int*)d_in[2];
    const float* W1 = (const float*)d_in[3];  const float* b1 = (const float*)d_in[4];
    const float* W2 = (const float*)d_in[5];  const float* b2 = (const float*)d_in[6];
    const float* Wfc = (const float*)d_in[7]; const float* bfc = (const float*)d_in[8];
    const float* Wii = (const float*)d_in[9];  const float* Wgi = (const float*)d_in[10];
    const float* Whi = (const float*)d_in[11]; const float* bi  = (const float*)d_in[12];
    const float* Wif = (const float*)d_in[13]; const float* Wgf = (const float*)d_in[14];
    const float* Whf = (const float*)d_in[15]; const float* bf_ = (const float*)d_in[16];
    const float* Wig = (const float*)d_in[17]; const float* Wgg = (const float*)d_in[18];
    const float* Whg = (const float*)d_in[19]; const float* bg  = (const float*)d_in[20];
    const float* Wio = (const float*)d_in[21]; const float* Wgo = (const float*)d_in[22];
    const float* Who = (const float*)d_in[23]; const float* bo  = (const float*)d_in[24];
    float* out = (float*)d_out;

    const int GSM = 2 * BUFW * 4;            // 147456 B gemm smem
    const int SSM = Nn * XS * 4;             // 135168 B spmm smem
    cudaFuncSetAttribute(k_gemm_mma<Nn, true>, cudaFuncAttributeMaxDynamicSharedMemorySize, GSM);
    cudaFuncSetAttribute(k_gemm_mma<Gg, false>, cudaFuncAttributeMaxDynamicSharedMemorySize, GSM);
    cudaFuncSetAttribute(k_spmm<true>, cudaFuncAttributeMaxDynamicSharedMemorySize, SSM);
    cudaFuncSetAttribute(k_spmm<false>, cudaFuncAttributeMaxDynamicSharedMemorySize, SSM);

    k_zero0<<<1, 32>>>();                                        // launch 0
    k_zero1<<<(NREP * Tt * D2 + 255) / 256, 256>>>();            // launch 1
    k_build<<<Tt, 1024>>>(ei);                                   // launch 2
    k_gemm_mma<Nn, true><<<dim3(8, Tt), 256, GSM>>>(xn, W1);     // launch 3  <- profiled
    k_spmm<true><<<dim3(4, Tt), 256, SSM>>>(b1);                 // launch 4
    k_gemm_mma<Gg, false><<<dim3(8, Tt), 256, GSM>>>(nullptr, W2); // 5
    k_spmm<false><<<dim3(4, Tt), 256, SSM>>>(b2);                // 6
    k_fc<<<Nn, 256>>>(Wfc);                                      // 7
    k_g2sum<<<(Tt * D2 + 255) / 256, 256>>>(bfc);                // 8
    k_pre<<<(Tt * 4 * Hh + 255) / 256, 256>>>(x_in,
                                              Wii, Wif, Wig, Wio,
                                              Wgi, Wgf, Wgg, Wgo,
                                              bi, bf_, bg, bo);  // 9
    k_lstm<<<LSTM_CTAS, 512>>>(Whi, Whf, Whg, Who, out, out_size); // 10

    (void)in_sizes; (void)n_in;
}

// round 15
// speedup vs baseline: 1.7751x; 1.7751x over previous
#include <cuda_runtime.h>
#include <cuda_bf16.h>
#include <math.h>
#include <cstdint>

#define Tt 96
#define Nn 1024
#define Gg 128
#define Hh 512
#define Ee 32768
#define ENe (Ee + Nn)
#define D2 56
#define INw 64
#define LSTM_CTAS 32
#define NREP 8

// ---------------- scratch ----------------
__device__ __align__(16) float g_XW[(size_t)Tt * Nn * Gg];
__device__ __align__(16) float g_HB[(size_t)Tt * Nn * Gg];
__device__ int   g_offs[Tt * (Nn + 1)];
__device__ __align__(8) int2 g_edge[(size_t)Tt * ENe];   // {src, w as float-bits}
__device__ float g_G2R[NREP * Tt * D2];
__device__ float g_G2[Tt * D2];
__device__ float g_pre[Tt * 4 * Hh];
__device__ float g_hbuf[2 * Hh];
__device__ unsigned g_cnt;

// ---------------- trivial zero kernels ----------------
__global__ void k_zero0() { if (threadIdx.x == 0 && blockIdx.x == 0) g_cnt = 0u; }
__global__ void k_zero1() {
    int i = blockIdx.x * blockDim.x + threadIdx.x;
    if (i < NREP * Tt * D2) g_G2R[i] = 0.f;
}

// ---------------- graph build: histogram + scan + CSR fill, one CTA per t ----------------
__global__ void __launch_bounds__(1024) k_build(const int* __restrict__ ei) {
    int t = blockIdx.x, tid = threadIdx.x;
    __shared__ int sc[Nn];
    __shared__ int cur[Nn];
    __shared__ float sdv[Nn];
    cur[tid] = 0;
    __syncthreads();
    for (int e = tid; e < Ee; e += 1024)
        atomicAdd(&cur[ei[(size_t)t * 2 * Ee + Ee + e] & (Nn - 1)], 1);
    __syncthreads();
    int c = cur[tid] + 1;                       // + self loop
    sdv[tid] = rsqrtf((float)c);
    sc[tid] = c;
    __syncthreads();
    for (int off = 1; off < Nn; off <<= 1) {
        int v = (tid >= off) ? sc[tid - off] : 0;
        __syncthreads();
        sc[tid] += v;
        __syncthreads();
    }
    int ex = sc[tid] - c;
    g_offs[t * (Nn + 1) + tid] = ex;
    if (tid == Nn - 1) g_offs[t * (Nn + 1) + Nn] = sc[tid];
    cur[tid] = ex;
    __syncthreads();
    for (int e = tid; e < ENe; e += 1024) {
        int s, d;
        if (e < Ee) {
            s = ei[(size_t)t * 2 * Ee + e] & (Nn - 1);
            d = ei[(size_t)t * 2 * Ee + Ee + e] & (Nn - 1);
        } else {
            s = d = e - Ee;
        }
        float w = sdv[s] * sdv[d];
        int pos = atomicAdd(&cur[d], 1);
        g_edge[(size_t)t * ENe + pos] = make_int2(s, __float_as_int(w));
    }
}

// ---------------- mma.sync helpers ----------------
__device__ __forceinline__ void mma16816(float* c, const uint32_t* a, uint32_t b0, uint32_t b1) {
    asm volatile(
        "mma.sync.aligned.m16n8k16.row.col.f32.bf16.bf16.f32 "
        "{%0,%1,%2,%3}, {%4,%5,%6,%7}, {%8,%9}, {%0,%1,%2,%3};"
        : "+f"(c[0]), "+f"(c[1]), "+f"(c[2]), "+f"(c[3])
        : "r"(a[0]), "r"(a[1]), "r"(a[2]), "r"(a[3]), "r"(b0), "r"(b1));
}
__device__ __forceinline__ uint32_t packbf2(float x, float y) {
    __nv_bfloat162 h = __floats2bfloat162_rn(x, y);
    return *(uint32_t*)&h;
}

// ---------------- pipelined tensor-core batched GEMM ----------------
#define RS 36
#define BUFW (4 * 128 * RS)
template <int KK, bool EXT>
__global__ void __launch_bounds__(256) k_gemm_mma(const float* __restrict__ Aext,
                                                  const float* __restrict__ B) {
    extern __shared__ uint32_t sm[];

    const int tid = threadIdx.x;
    const int wid = tid >> 5, lane = tid & 31;
    const int warp_m = wid & 3, warp_n = wid >> 2;
    const int t = blockIdx.y;
    const size_t Astr = EXT ? (size_t)Nn * Nn : (size_t)Nn * Gg;
    const float* At = (EXT ? Aext : (const float*)g_HB) + (size_t)t * Astr + (size_t)blockIdx.x * 128 * KK;
    float* Ct = g_XW + ((size_t)t * Nn + (size_t)blockIdx.x * 128) * Gg;

    float acc[2][8][4];
#pragma unroll
    for (int mf = 0; mf < 2; mf++)
#pragma unroll
        for (int nf = 0; nf < 8; nf++)
#pragma unroll
            for (int r = 0; r < 4; r++) acc[mf][nf][r] = 0.f;

    const int lr = lane >> 2;
    const int lk = lane & 3;
    const int r0a = tid >> 4, qa = tid & 15;
    const int k2b = tid >> 7, nb = tid & 127;

    float4 aR[8];
    float2 bR[16];

#pragma unroll
    for (int j = 0; j < 8; j++)
        aR[j] = *(const float4*)(At + (size_t)(r0a + 16 * j) * KK + qa * 4);
#pragma unroll
    for (int j = 0; j < 16; j++) {
        int k = 2 * (k2b + 2 * j);
        bR[j] = make_float2(B[(size_t)k * Gg + nb], B[(size_t)(k + 1) * Gg + nb]);
    }

    constexpr int NK = KK / 64;
    for (int ki = 0; ki < NK; ki++) {
        uint32_t* base = sm + (ki & 1) * BUFW;
        uint32_t* smAh = base;
        uint32_t* smAl = base + 128 * RS;
        uint32_t* smBh = base + 2 * 128 * RS;
        uint32_t* smBl = base + 3 * 128 * RS;

#pragma unroll
        for (int j = 0; j < 8; j++) {
            float4 v = aR[j];
            float hx = __bfloat162float(__float2bfloat16_rn(v.x));
            float hy = __bfloat162float(__float2bfloat16_rn(v.y));
            float hz = __bfloat162float(__float2bfloat16_rn(v.z));
            float hw = __bfloat162float(__float2bfloat16_rn(v.w));
            int idx = (r0a + 16 * j) * RS + qa * 2;
            smAh[idx]     = packbf2(v.x, v.y);
            smAh[idx + 1] = packbf2(v.z, v.w);
            smAl[idx]     = packbf2(v.x - hx, v.y - hy);
            smAl[idx + 1] = packbf2(v.z - hz, v.w - hw);
        }
        {
            int rho = ((nb >> 3) & 3) << 3;
#pragma unroll
            for (int j = 0; j < 16; j++) {
                int k2 = k2b + 2 * j;
                float2 v = bR[j];
                float h0 = __bfloat162float(__float2bfloat16_rn(v.x));
                float h1 = __bfloat162float(__float2bfloat16_rn(v.y));
                int idx = nb * RS + (k2 ^ rho);
                smBh[idx] = packbf2(v.x, v.y);
                smBl[idx] = packbf2(v.x - h0, v.y - h1);
            }
        }
        __syncthreads();

        if (ki + 1 < NK) {
            int k0n = (ki + 1) * 64;
#pragma unroll
            for (int j = 0; j < 8; j++)
                aR[j] = *(const float4*)(At + (size_t)(r0a + 16 * j) * KK + k0n + qa * 4);
#pragma unroll
            for (int j = 0; j < 16; j++) {
                int k = k0n + 2 * (k2b + 2 * j);
                bR[j] = make_float2(B[(size_t)k * Gg + nb], B[(size_t)(k + 1) * Gg + nb]);
            }
        }

#pragma unroll
        for (int ks = 0; ks < 4; ks++) {
            uint32_t ah[2][4], al[2][4];
#pragma unroll
            for (int mf = 0; mf < 2; mf++) {
                int rm = warp_m * 32 + mf * 16 + lr;
                int kw = ks * 8 + lk;
                ah[mf][0] = smAh[rm * RS + kw];
                ah[mf][1] = smAh[(rm + 8) * RS + kw];
                ah[mf][2] = smAh[rm * RS + kw + 4];
                ah[mf][3] = smAh[(rm + 8) * RS + kw + 4];
                al[mf][0] = smAl[rm * RS + kw];
                al[mf][1] = smAl[(rm + 8) * RS + kw];
                al[mf][2] = smAl[rm * RS + kw + 4];
                al[mf][3] = smAl[(rm + 8) * RS + kw + 4];
            }
#pragma unroll
            for (int nf = 0; nf < 8; nf++) {
                int cn = warp_n * 64 + nf * 8 + lr;
                int rho = ((cn >> 3) & 3) << 3;
                int kw = ks * 8 + lk;
                uint32_t bh0 = smBh[cn * RS + (kw ^ rho)];
                uint32_t bh1 = smBh[cn * RS + ((kw + 4) ^ rho)];
                uint32_t bl0 = smBl[cn * RS + (kw ^ rho)];
                uint32_t bl1 = smBl[cn * RS + ((kw + 4) ^ rho)];
#pragma unroll
                for (int mf = 0; mf < 2; mf++) {
                    mma16816(acc[mf][nf], ah[mf], bh0, bh1);
                    mma16816(acc[mf][nf], ah[mf], bl0, bl1);
                    mma16816(acc[mf][nf], al[mf], bh0, bh1);
                }
            }
        }
    }

#pragma unroll
    for (int mf = 0; mf < 2; mf++) {
        int row = warp_m * 32 + mf * 16 + lr;
#pragma unroll
        for (int nf = 0; nf < 8; nf++) {
            int col = warp_n * 64 + nf * 8 + lk * 2;
            float* base = Ct + (size_t)row * Gg + col;
            *(float2*)base = make_float2(acc[mf][nf][0], acc[mf][nf][1]);
            *(float2*)(base + 8 * Gg) = make_float2(acc[mf][nf][2], acc[mf][nf][3]);
        }
    }
}

// ---------------- SpMM v2 (reverted, from best run): warp per node, float4 per lane ----------------
template <bool RELU>
__global__ void __launch_bounds__(128) k_spmm(const float* __restrict__ bias) {
    int t = blockIdx.y;
    int warp = threadIdx.x >> 5, lane = threadIdx.x & 31;
    int n = blockIdx.x * 4 + warp;
    int beg = g_offs[t * (Nn + 1) + n], end = g_offs[t * (Nn + 1) + n + 1];
    const int2* ep = g_edge + (size_t)t * ENe;
    const float4* X4 = (const float4*)(g_XW + (size_t)t * Nn * Gg);
    float4 acc = *(const float4*)(bias + lane * 4);
    float4 a = make_float4(0.f, 0.f, 0.f, 0.f);

    int e = beg;
    for (; e + 32 <= end; e += 32) {
        int2 er = ep[e + lane];
#pragma unroll
        for (int j = 0; j < 32; j++) {
            int sj = __shfl_sync(0xffffffffu, er.x, j);
            float wj = __uint_as_float(__shfl_sync(0xffffffffu, er.y, j));
            float4 x = X4[(size_t)sj * 32 + lane];
            a.x += wj * x.x; a.y += wj * x.y; a.z += wj * x.z; a.w += wj * x.w;
        }
    }
    if (e < end) {
        int2 er = ep[min(e + lane, end - 1)];
        int cnt = end - e;
        for (int j = 0; j < cnt; j++) {
            int sj = __shfl_sync(0xffffffffu, er.x, j);
            float wj = __uint_as_float(__shfl_sync(0xffffffffu, er.y, j));
            float4 x = X4[(size_t)sj * 32 + lane];
            a.x += wj * x.x; a.y += wj * x.y; a.z += wj * x.z; a.w += wj * x.w;
        }
    }
    acc.x += a.x; acc.y += a.y; acc.z += a.z; acc.w += a.w;
    if (RELU) {
        acc.x = fmaxf(acc.x, 0.f); acc.y = fmaxf(acc.y, 0.f);
        acc.z = fmaxf(acc.z, 0.f); acc.w = fmaxf(acc.w, 0.f);
    }
    *(float4*)(g_HB + ((size_t)t * Nn + n) * Gg + lane * 4) = acc;
}

// ---------------- FC: per-node CTA, 4 timesteps/iter, replicated accumulators ----------------
__global__ void __launch_bounds__(256) k_fc(const float* __restrict__ Wfc) {
    int n = blockIdx.x;
    int tid = threadIdx.x;
    __shared__ float Wsm[Gg * D2];
    __shared__ float hs[4][Gg];
    for (int i = tid; i < Gg * D2; i += 256)
        Wsm[i] = Wfc[(size_t)n * Gg * D2 + i];
    __syncthreads();
    int rep = n & (NREP - 1);
    for (int t0 = 0; t0 < Tt; t0 += 4) {
        for (int i = tid; i < 4 * Gg; i += 256)
            hs[i >> 7][i & 127] = g_HB[((size_t)(t0 + (i >> 7)) * Nn + n) * Gg + (i & 127)];
        __syncthreads();
        if (tid < 4 * D2) {
            int tt = tid / D2, d = tid % D2;
            float acc = 0.f;
#pragma unroll 8
            for (int k = 0; k < Gg; k++) acc += hs[tt][k] * Wsm[k * D2 + d];
            atomicAdd(&g_G2R[(rep * Tt + t0 + tt) * D2 + d], acc);
        }
        __syncthreads();
    }
}

// ---------------- sum replicas + bias + relu ----------------
__global__ void k_g2sum(const float* __restrict__ bfc) {
    int i = blockIdx.x * blockDim.x + threadIdx.x;
    if (i >= Tt * D2) return;
    int d = i % D2;
    float s = bfc[d];
#pragma unroll
    for (int r = 0; r < NREP; r++) s += g_G2R[r * Tt * D2 + i];
    g_G2[i] = fmaxf(s, 0.f);
}

// ---------------- LSTM pre-activations ----------------
__global__ void k_pre(const float* __restrict__ x,
                      const float* __restrict__ Wi0, const float* __restrict__ Wi1,
                      const float* __restrict__ Wi2, const float* __restrict__ Wi3,
                      const float* __restrict__ Wg0, const float* __restrict__ Wg1,
                      const float* __restrict__ Wg2, const float* __restrict__ Wg3,
                      const float* __restrict__ b0, const float* __restrict__ b1,
                      const float* __restrict__ b2, const float* __restrict__ b3) {
    int gid = blockIdx.x * blockDim.x + threadIdx.x;
    if (gid >= Tt * 4 * Hh) return;
    int j = gid & (Hh - 1);
    int gate = (gid >> 9) & 3;
    int t = gid >> 11;
    const float* Wi = gate == 0 ? Wi0 : gate == 1 ? Wi1 : gate == 2 ? Wi2 : Wi3;
    const float* Wg = gate == 0 ? Wg0 : gate == 1 ? Wg1 : gate == 2 ? Wg2 : Wg3;
    const float* bb = gate == 0 ? b0 : gate == 1 ? b1 : gate == 2 ? b2 : b3;
    float acc = bb[j];
#pragma unroll 8
    for (int k = 0; k < INw; k++) acc += x[t * INw + k] * Wi[k * Hh + j];
#pragma unroll 8
    for (int d = 0; d < D2; d++) acc += g_G2[t * D2 + d] * Wg[d * Hh + j];
    g_pre[gid] = acc;
}

// ---------------- persistent recurrent LSTM ----------------
__global__ void __launch_bounds__(512, 1) k_lstm(const float* __restrict__ Whi,
                                                 const float* __restrict__ Whf,
                                                 const float* __restrict__ Whg,
                                                 const float* __restrict__ Who,
                                                 float* __restrict__ out, int out_size) {
    int tid = threadIdx.x, warp = tid >> 5, lane = tid & 31;
    int unit = blockIdx.x * 16 + warp;
    int gate = lane >> 3, q = lane & 7;
    const float* Wh = gate == 0 ? Whi : gate == 1 ? Whf : gate == 2 ? Whg : Who;

    float w[64];
#pragma unroll
    for (int mm = 0; mm < 16; mm++)
#pragma unroll
        for (int r = 0; r < 4; r++)
            w[mm * 4 + r] = Wh[(size_t)((q + 8 * mm) * 4 + r) * Hh + unit];

    __shared__ float sh[Hh];
    sh[tid] = 0.f;
    __syncthreads();
    float c = 0.f;

    for (int s = 0; s < Tt; s++) {
        const float4* sh4 = (const float4*)sh;
        float acc = 0.f;
#pragma unroll
        for (int mm = 0; mm < 16; mm++) {
            float4 v = sh4[q + 8 * mm];
            acc += w[mm * 4 + 0] * v.x + w[mm * 4 + 1] * v.y +
                   w[mm * 4 + 2] * v.z + w[mm * 4 + 3] * v.w;
        }
        acc += __shfl_xor_sync(0xffffffffu, acc, 4);
        acc += __shfl_xor_sync(0xffffffffu, acc, 2);
        acc += __shfl_xor_sync(0xffffffffu, acc, 1);
        acc += g_pre[(s * 4 + gate) * Hh + unit];
        float vi = __shfl_sync(0xffffffffu, acc, 0);
        float vf = __shfl_sync(0xffffffffu, acc, 8);
        float vg = __shfl_sync(0xffffffffu, acc, 16);
        float vo = __shfl_sync(0xffffffffu, acc, 24);
        vi = 1.f / (1.f + expf(-vi));
        vf = 1.f / (1.f + expf(-vf));
        vo = 1.f / (1.f + expf(-vo));
        vg = tanhf(vg);
        c = vf * c + vi * vg;
        float h = vo * tanhf(c);
        if (lane == 0) {
            g_hbuf[(s & 1) * Hh + unit] = h;
            if (s * Hh + unit < out_size) out[s * Hh + unit] = h;
            if (s == Tt - 1) {
                if (Tt * Hh + unit < out_size) out[Tt * Hh + unit] = h;
                if (Tt * Hh + Hh + unit < out_size) out[Tt * Hh + Hh + unit] = c;
            }
            __threadfence();
        }
        __syncthreads();
        if (tid == 0) {
            atomicAdd(&g_cnt, 1u);
            unsigned target = (unsigned)(s + 1) * LSTM_CTAS;
            while (*((volatile unsigned*)&g_cnt) < target) {}
            __threadfence();
        }
        __syncthreads();
        sh[tid] = *((volatile float*)&g_hbuf[(s & 1) * Hh + tid]);
        __syncthreads();
    }
}

// ---------------- launch ----------------
extern "C" void kernel_launch(void* const* d_in, const int* in_sizes, int n_in,
                              void* d_out, int out_size) {
    const float* x_in = (const float*)d_in[0];
    const float* xn   = (const float*)d_in[1];
    const int*   ei   = (const int*)d_in[2];
    const float* W1 = (const float*)d_in[3];  const float* b1 = (const float*)d_in[4];
    const float* W2 = (const float*)d_in[5];  const float* b2 = (const float*)d_in[6];
    const float* Wfc = (const float*)d_in[7]; const float* bfc = (const float*)d_in[8];
    const float* Wii = (const float*)d_in[9];  const float* Wgi = (const float*)d_in[10];
    const float* Whi = (const float*)d_in[11]; const float* bi  = (const float*)d_in[12];
    const float* Wif = (const float*)d_in[13]; const float* Wgf = (const float*)d_in[14];
    const float* Whf = (const float*)d_in[15]; const float* bf_ = (const float*)d_in[16];
    const float* Wig = (const float*)d_in[17]; const float* Wgg = (const float*)d_in[18];
    const float* Whg = (const float*)d_in[19]; const float* bg  = (const float*)d_in[20];
    const float* Wio = (const float*)d_in[21]; const float* Wgo = (const float*)d_in[22];
    const float* Who = (const float*)d_in[23]; const float* bo  = (const float*)d_in[24];
    float* out = (float*)d_out;

    const int GSM = 2 * BUFW * 4;            // 147456 B gemm smem
    cudaFuncSetAttribute(k_gemm_mma<Nn, true>, cudaFuncAttributeMaxDynamicSharedMemorySize, GSM);
    cudaFuncSetAttribute(k_gemm_mma<Gg, false>, cudaFuncAttributeMaxDynamicSharedMemorySize, GSM);

    k_zero0<<<1, 32>>>();                                        // launch 0
    k_build<<<Tt, 1024>>>(ei);                                   // launch 1
    k_gemm_mma<Nn, true><<<dim3(8, Tt), 256, GSM>>>(xn, W1);     // launch 2
    k_spmm<true><<<dim3(Nn / 4, Tt), 128>>>(b1);                 // launch 3  <- profiled
    k_gemm_mma<Gg, false><<<dim3(8, Tt), 256, GSM>>>(nullptr, W2); // 4
    k_spmm<false><<<dim3(Nn / 4, Tt), 128>>>(b2);                // 5
    k_zero1<<<(NREP * Tt * D2 + 255) / 256, 256>>>();            // 6
    k_fc<<<Nn, 256>>>(Wfc);                                      // 7
    k_g2sum<<<(Tt * D2 + 255) / 256, 256>>>(bfc);                // 8
    k_pre<<<(Tt * 4 * Hh + 255) / 256, 256>>>(x_in,
                                              Wii, Wif, Wig, Wio,
                                              Wgi, Wgf, Wgg, Wgo,
                                              bi, bf_, bg, bo);  // 9
    k_lstm<<<LSTM_CTAS, 512>>>(Whi, Whf, Whg, Who, out, out_size); // 10

    (void)in_sizes; (void)n_in;
}